// round 5
// baseline (speedup 1.0000x reference)
#include <cuda_runtime.h>

// Problem shape (fixed by the dataset)
#define Bn 8
#define Ln 4096
#define Mn 2048
#define Dn 512
#define CK 32              // chunk length along M
#define NC (Mn / CK)       // 64 chunks per batch row
#define D4 (Dn / 4)        // 128 float4 per row

// -------- device scratch (static globals: allocation-free) --------
__device__ float  g_decay[Bn * Mn];          // per-chunk-slot decay (1.0 for invalid)
__device__ float  g_Ac[Bn * NC];             // per-chunk decay product (precomputed)
__device__ float4 g_aggB[Bn * NC * D4];      // per-chunk local scan aggregate B_c
__device__ volatile int g_flag[Bn * NC];     // 0 = not ready, 1 = aggregate published
__device__ int    g_cidx[Bn * Ln];           // cumsum(token_mask)-1 per token (>= -1)
__device__ int    g_pos[Bn * Mn];            // seq position of m-th selected token (Ln if invalid)
__device__ int    g_maskflag;                // 1 = mask stored as 1-byte, 0 = 4-byte ints

// -------- K0: detect token_mask element width --------
__global__ void k_detect(const unsigned char* __restrict__ mb,
                         const int* __restrict__ counts) {
    __shared__ int sred[8];
    int tid = threadIdx.x;
    int s = 0;
    for (int i = tid; i < Ln; i += 256) s += (mb[i] != 0);
    #pragma unroll
    for (int o = 16; o; o >>= 1) s += __shfl_down_sync(0xFFFFFFFFu, s, o);
    if ((tid & 31) == 0) sred[tid >> 5] = s;
    __syncthreads();
    if (tid == 0) {
        int t = 0;
        #pragma unroll
        for (int w = 0; w < 8; w++) t += sred[w];
        g_maskflag = (t == counts[0]) ? 1 : 0;
    }
}

// -------- K1: compaction (decay, cidx, pos) + chunk A products + flag reset --------
__global__ __launch_bounds__(512) void k_prep(const float* __restrict__ prob,
                                              const void* __restrict__ maskbuf) {
    const int b   = blockIdx.x;
    const int tid = threadIdx.x;           // 512 threads, 8 tokens each
    const unsigned char* mb8  = (const unsigned char*)maskbuf;
    const int*           mb32 = (const int*)maskbuf;
    const int flag = g_maskflag;

    int m[8];
    int s = 0;
    const int base = tid * 8;
    #pragma unroll
    for (int j = 0; j < 8; j++) {
        int l = base + j;
        int v = flag ? (mb8[b * Ln + l] != 0) : (mb32[b * Ln + l] != 0);
        m[j] = v;
        s += v;
    }

    // block-wide exclusive scan of per-thread counts
    const int lane = tid & 31, wid = tid >> 5;
    int inc = s;
    #pragma unroll
    for (int o = 1; o < 32; o <<= 1) {
        int n = __shfl_up_sync(0xFFFFFFFFu, inc, o);
        if (lane >= o) inc += n;
    }
    __shared__ int wsum[16];
    if (lane == 31) wsum[wid] = inc;
    __syncthreads();
    if (wid == 0 && lane < 16) {
        int v = wsum[lane];
        #pragma unroll
        for (int o = 1; o < 16; o <<= 1) {
            int n = __shfl_up_sync(0x0000FFFFu, v, o);
            if (lane >= o) v += n;
        }
        wsum[lane] = v;
    }
    __syncthreads();
    const int excl = inc - s + ((wid > 0) ? wsum[wid - 1] : 0);

    // init: invalid slots -> decay 1.0 (state carries), pos = Ln (empty span)
    for (int i = tid; i < Mn; i += 512) {
        g_decay[b * Mn + i] = 1.0f;
        g_pos[b * Mn + i]   = Ln;
    }
    __syncthreads();

    int run = excl;
    #pragma unroll
    for (int j = 0; j < 8; j++) {
        const int l = base + j;
        if (m[j]) {
            float p = prob[b * Ln + l];
            g_decay[b * Mn + run] = fminf(fmaxf(1.0f - p, 0.0f), 1.0f);
            g_pos[b * Mn + run]   = l;
            run++;
        }
        g_cidx[b * Ln + l] = run - 1;
    }
    __syncthreads();

    // per-chunk total decay product + lookback flag reset
    if (tid < NC) {
        const float* dd = g_decay + b * Mn + tid * CK;
        float p = 1.0f;
        #pragma unroll
        for (int t = 0; t < CK; t++) p *= dd[t];
        g_Ac[b * NC + tid]   = p;
        g_flag[b * NC + tid] = 0;
    }
}

// -------- K2 (fused): local scan -> publish aggregate -> lookback carry ->
//          gather+fixup+residual-add directly from smem, plus new_state --------
__global__ __launch_bounds__(128) void k_main(const float4* __restrict__ hidden,
                                              const float4* __restrict__ residual,
                                              const float4* __restrict__ state4,
                                              const int* __restrict__ counts,
                                              float4* __restrict__ out,
                                              float4* __restrict__ out_ns) {
    extern __shared__ float4 hs[];             // [CK][D4] local EMA states (64 KB)
    __shared__ float sd[CK], sod[CK], spp[CK];

    const int blk = blockIdx.x;                // b*NC + c
    const int b = blk >> 6, c = blk & (NC - 1);
    const int tid = threadIdx.x;

    if (tid < CK) {
        float d = g_decay[b * Mn + c * CK + tid];
        sd[tid]  = d;
        sod[tid] = 1.0f - d;
    }
    __syncthreads();
    if (tid == 0) {
        float p = 1.0f;
        #pragma unroll
        for (int t = 0; t < CK; t++) { p *= sd[t]; spp[t] = p; }
    }

    // ---- local scan (h0 = 0) with depth-8 prefetch ring; rows land in smem ----
    const size_t rowbase = (size_t)(b * Mn + c * CK) * D4 + tid;
    const float4* src = hidden + rowbase;
    float4 buf[8];
    #pragma unroll
    for (int i = 0; i < 8; i++) buf[i] = src[(size_t)i * D4];

    float4 h = make_float4(0.f, 0.f, 0.f, 0.f);
    #pragma unroll
    for (int t = 0; t < CK; t++) {
        float4 x = buf[t & 7];
        if (t + 8 < CK) buf[t & 7] = src[(size_t)(t + 8) * D4];
        const float d = sd[t], od = sod[t];
        h.x = fmaf(d, h.x, od * x.x);
        h.y = fmaf(d, h.y, od * x.y);
        h.z = fmaf(d, h.z, od * x.z);
        h.w = fmaf(d, h.w, od * x.w);
        hs[t * D4 + tid] = h;
    }

    // ---- publish aggregate B_c, then set flag ----
    g_aggB[(size_t)blk * D4 + tid] = h;
    __threadfence();
    __syncthreads();                           // also makes spp visible to everyone
    if (tid == 0) g_flag[blk] = 1;

    // ---- lookback: carry = sum_{j<c} (prod_{j<i<c} A_i) B_j + (prod A) * state ----
    float4 carry;
    {
        const float4 st = state4[b * D4 + tid];
        float4 acc = make_float4(0.f, 0.f, 0.f, 0.f);
        float prod = 1.0f;
        int j = c - 1;
        while (j >= 0) {
            const int jw = (j >= 7) ? j - 7 : 0;  // window [jw .. j], up to 8 chunks
            bool ok;
            do {
                ok = true;
                for (int k = j; k >= jw; k--) ok &= (g_flag[b * NC + k] != 0);
            } while (!ok);
            __threadfence();
            const int n = j - jw + 1;
            float4 v[8];
            #pragma unroll
            for (int k = 0; k < 8; k++)
                if (k < n) v[k] = __ldcg(&g_aggB[(size_t)(b * NC + (j - k)) * D4 + tid]);
            #pragma unroll
            for (int k = 0; k < 8; k++) {
                if (k < n) {
                    acc.x = fmaf(prod, v[k].x, acc.x);
                    acc.y = fmaf(prod, v[k].y, acc.y);
                    acc.z = fmaf(prod, v[k].z, acc.z);
                    acc.w = fmaf(prod, v[k].w, acc.w);
                    prod *= g_Ac[b * NC + (j - k)];
                }
            }
            j = jw - 1;
        }
        carry.x = fmaf(prod, st.x, acc.x);
        carry.y = fmaf(prod, st.y, acc.y);
        carry.z = fmaf(prod, st.z, acc.z);
        carry.w = fmaf(prod, st.w, acc.w);
    }

    // ---- new_state: block owning chunk of (count-1) writes it ----
    const int cnt = counts[b];
    if (out_ns) {
        if (cnt > 0) {
            if (((cnt - 1) >> 5) == c) {
                const int t = (cnt - 1) & (CK - 1);
                const float pp = spp[t];
                float4 hv = hs[t * D4 + tid];
                float4 ns;
                ns.x = fmaf(pp, carry.x, hv.x);
                ns.y = fmaf(pp, carry.y, hv.y);
                ns.z = fmaf(pp, carry.z, hv.z);
                ns.w = fmaf(pp, carry.w, hv.w);
                out_ns[b * D4 + tid] = ns;
            }
        } else if (c == 0) {
            out_ns[b * D4 + tid] = state4[b * D4 + tid];
        }
    }

    // ---- output span: rows whose cidx falls in this chunk (c==0 also covers cidx=-1) ----
    const int sidx = c * CK;
    const int start = (c == 0) ? 0 : g_pos[b * Mn + sidx];
    const int eidx = sidx + CK;
    const int end = (eidx < Mn) ? g_pos[b * Mn + eidx] : Ln;
    const int* cix = g_cidx + b * Ln;
    const size_t obase = (size_t)b * Ln * D4 + tid;

    #pragma unroll 4
    for (int l = start; l < end; l++) {
        const int ci = cix[l];
        const size_t o = obase + (size_t)l * D4;
        float4 r = residual[o];
        float4 v = r;
        const int t = ci - sidx;
        if (t >= 0) {
            const float pp = spp[t];
            float4 hv = hs[t * D4 + tid];
            v.x = r.x + fmaf(pp, carry.x, hv.x);
            v.y = r.y + fmaf(pp, carry.y, hv.y);
            v.z = r.z + fmaf(pp, carry.z, hv.z);
            v.w = r.w + fmaf(pp, carry.w, hv.w);
        }
        out[o] = v;
    }
}

extern "C" void kernel_launch(void* const* d_in, const int* in_sizes, int n_in,
                              void* d_out, int out_size) {
    const float* hidden   = (const float*)d_in[0];  // (B,M,D)
    const float* residual = (const float*)d_in[1];  // (B,L,D)
    const float* prob     = (const float*)d_in[2];  // (B,L)
    const float* state    = (const float*)d_in[3];  // (B,D)
    const void*  mask     = d_in[4];                // (B,L) bool (width auto-detected)
    const int*   counts   = (const int*)d_in[5];    // (B,)

    float* out = (float*)d_out;
    const long long main_elems = (long long)Bn * Ln * Dn;
    float4* ns = (out_size >= main_elems + Bn * Dn)
                     ? (float4*)(out + main_elems) : nullptr;

    const int smem_bytes = CK * D4 * (int)sizeof(float4);   // 64 KB
    static int attr_set = 0;
    if (!attr_set) {
        cudaFuncSetAttribute(k_main, cudaFuncAttributeMaxDynamicSharedMemorySize,
                             smem_bytes);
        attr_set = 1;
    }

    k_detect<<<1, 256>>>((const unsigned char*)mask, (const int*)d_in[5]);
    k_prep  <<<Bn, 512>>>(prob, mask);
    k_main  <<<Bn * NC, 128, smem_bytes>>>((const float4*)hidden,
                                           (const float4*)residual,
                                           (const float4*)state,
                                           (const int*)d_in[5],
                                           (float4*)out, ns);
}

// round 6
// speedup vs baseline: 2.6688x; 2.6688x over previous
#include <cuda_runtime.h>

// Problem shape (fixed by the dataset)
#define Bn 8
#define Ln 4096
#define Mn 2048
#define Dn 512
#define CK 32              // chunk length along M
#define NC (Mn / CK)       // 64 chunks
#define D4 (Dn / 4)        // 128 float4 per row

// -------- device scratch (static globals: allocation-free) --------
__device__ float g_decay[Bn * Mn];        // per-chunk-slot decay (1.0 for invalid slots)
__device__ float g_pp[Bn * Mn];           // within-chunk inclusive prefix products of decay
__device__ float g_Ac[Bn * NC];           // per-chunk total decay product
__device__ float g_Bc[Bn * NC * Dn];      // per-chunk local scan result (h0 = 0)
__device__ float g_carry[Bn * NC * Dn];   // state entering each chunk
__device__ int   g_cidx[Bn * Ln];         // inclusive cumsum(token_mask) - 1  (>= -1)
__device__ float g_ema[Bn * Mn * Dn];     // local (h0=0) EMA states, all t

// -------- K1: per-batch compaction with in-block mask-width detection --------
__global__ __launch_bounds__(512) void k_prep(const float* __restrict__ prob,
                                              const void* __restrict__ maskbuf,
                                              const int* __restrict__ counts) {
    const int b   = blockIdx.x;
    const int tid = threadIdx.x;           // 512 threads, 8 tokens each
    const unsigned char* mb8  = (const unsigned char*)maskbuf;
    const int*           mb32 = (const int*)maskbuf;

    // ---- detect mask element width for this row:
    // u8 layout: nonzero bytes in bytes [b*Ln, (b+1)*Ln) == counts[b] (1024..2048).
    // i32 layout: those bytes cover 1024 ints (0/1 each) -> nonzero bytes <= 1024,
    // cannot equal counts[b] except vanishing-probability corner. ----
    __shared__ int wred[16];
    __shared__ int sflag;
    {
        int s = 0;
        for (int i = tid; i < Ln; i += 512) s += (mb8[b * Ln + i] != 0);
        #pragma unroll
        for (int o = 16; o; o >>= 1) s += __shfl_down_sync(0xFFFFFFFFu, s, o);
        if ((tid & 31) == 0) wred[tid >> 5] = s;
        __syncthreads();
        if (tid == 0) {
            int t = 0;
            #pragma unroll
            for (int w = 0; w < 16; w++) t += wred[w];
            sflag = (t == counts[b]) ? 1 : 0;
        }
        __syncthreads();
    }
    const int flag = sflag;

    int m[8];
    int s = 0;
    const int base = tid * 8;
    #pragma unroll
    for (int j = 0; j < 8; j++) {
        int l = base + j;
        int v = flag ? (mb8[b * Ln + l] != 0) : (mb32[b * Ln + l] != 0);
        m[j] = v;
        s += v;
    }

    // block-wide exclusive scan of per-thread counts
    const int lane = tid & 31, wid = tid >> 5;
    int inc = s;
    #pragma unroll
    for (int o = 1; o < 32; o <<= 1) {
        int n = __shfl_up_sync(0xFFFFFFFFu, inc, o);
        if (lane >= o) inc += n;
    }
    __shared__ int wsum[16];
    if (lane == 31) wsum[wid] = inc;
    __syncthreads();
    if (wid == 0 && lane < 16) {
        int v = wsum[lane];
        #pragma unroll
        for (int o = 1; o < 16; o <<= 1) {
            int n = __shfl_up_sync(0x0000FFFFu, v, o);
            if (lane >= o) v += n;
        }
        wsum[lane] = v;
    }
    __syncthreads();
    const int excl = inc - s + ((wid > 0) ? wsum[wid - 1] : 0);

    // init decay row to 1.0 (invalid slots: decay=1 -> state carries, matches ref)
    for (int i = tid; i < Mn; i += 512) g_decay[b * Mn + i] = 1.0f;
    __syncthreads();

    int run = excl;
    #pragma unroll
    for (int j = 0; j < 8; j++) {
        const int l = base + j;
        if (m[j]) {
            float p = prob[b * Ln + l];
            float dcy = fminf(fmaxf(1.0f - p, 0.0f), 1.0f);
            g_decay[b * Mn + run] = dcy;
            run++;
        }
        g_cidx[b * Ln + l] = run - 1;
    }
}

// -------- K2: per-chunk local EMA scan (h0 = 0), prefix products, A_c, B_c --------
__global__ __launch_bounds__(128) void k_scan(const float4* __restrict__ hidden) {
    const int blk = blockIdx.x;            // b*NC + c
    const int b = blk / NC, c = blk % NC;
    const int tid = threadIdx.x;           // 128 threads = one float4 column each

    __shared__ float sd[CK], sod[CK];
    if (tid < CK) {
        float d = g_decay[b * Mn + c * CK + tid];
        sd[tid]  = d;
        sod[tid] = 1.0f - d;
    }
    __syncthreads();

    if (tid == 0) {
        float p = 1.0f;
        #pragma unroll
        for (int t = 0; t < CK; t++) {
            p *= sd[t];
            g_pp[b * Mn + c * CK + t] = p;
        }
        g_Ac[blk] = p;
    }

    const size_t rowbase = (size_t)(b * Mn + c * CK) * D4 + tid;
    const float4* src = hidden + rowbase;
    float4*       dst = ((float4*)g_ema) + rowbase;

    // depth-8 prefetch ring: keeps 8 LDG.128 in flight per thread
    float4 buf[8];
    #pragma unroll
    for (int i = 0; i < 8; i++) buf[i] = src[(size_t)i * D4];

    float4 h = make_float4(0.f, 0.f, 0.f, 0.f);
    #pragma unroll
    for (int t = 0; t < CK; t++) {
        float4 x = buf[t & 7];
        if (t + 8 < CK) buf[t & 7] = src[(size_t)(t + 8) * D4];
        const float d = sd[t], od = sod[t];
        h.x = fmaf(d, h.x, od * x.x);
        h.y = fmaf(d, h.y, od * x.y);
        h.z = fmaf(d, h.z, od * x.z);
        h.w = fmaf(d, h.w, od * x.w);
        dst[(size_t)t * D4] = h;
    }
    ((float4*)g_Bc)[(size_t)blk * D4 + tid] = h;
}

// -------- K3: sequential chunk-carry combine + new_state --------
// All 64 chunk aggregates loaded upfront into registers (MLP=64, single L2
// latency), then a 64-FMA dependent chain. Grid is tiny; latency is all.
__global__ __launch_bounds__(128) void k_carry(const float* __restrict__ state,
                                               const int* __restrict__ counts,
                                               float* __restrict__ out_ns) {
    const int idx = blockIdx.x * 128 + threadIdx.x;   // (b,d) flat
    const int b = idx >> 9;          // / Dn
    const int d = idx & (Dn - 1);    // % Dn

    __shared__ float sA[NC];
    if (threadIdx.x < NC) sA[threadIdx.x] = g_Ac[b * NC + threadIdx.x];
    __syncthreads();

    const float* Bc = g_Bc    + (size_t)b * NC * Dn + d;
    float*       Cr = g_carry + (size_t)b * NC * Dn + d;

    float buf[NC];
    #pragma unroll
    for (int c = 0; c < NC; c++) buf[c] = __ldcg(&Bc[(size_t)c * Dn]);

    float carry = state[idx];
    #pragma unroll
    for (int c = 0; c < NC; c++) {
        Cr[(size_t)c * Dn] = carry;
        carry = fmaf(sA[c], carry, buf[c]);
    }

    if (out_ns) {
        const int cnt = counts[b];
        float ns;
        if (cnt > 0) {
            const int t = cnt - 1, cl = t / CK;
            ns = g_ema[(size_t)(b * Mn + t) * Dn + d] +
                 g_pp[b * Mn + t] * g_carry[(size_t)(b * NC + cl) * Dn + d];
        } else {
            ns = state[idx];
        }
        out_ns[idx] = ns;
    }
}

// -------- K4: gather + carry fix-up + residual add --------
__global__ __launch_bounds__(256) void k_out(const float4* __restrict__ residual,
                                             float4* __restrict__ out) {
    const int row = blockIdx.x * 2 + (threadIdx.x >> 7);  // (b*Ln + l)
    const int t   = threadIdx.x & 127;
    const int b   = row / Ln;
    const int ci  = g_cidx[row];

    const size_t o = (size_t)row * D4 + t;
    float4 r = residual[o];
    float4 v = r;
    if (ci >= 0) {
        const float pp = g_pp[b * Mn + ci];
        const int   cc = ci / CK;
        float4 e  = ((const float4*)g_ema)[(size_t)(b * Mn + ci) * D4 + t];
        float4 cr = ((const float4*)g_carry)[(size_t)(b * NC + cc) * D4 + t];
        v.x = r.x + fmaf(pp, cr.x, e.x);
        v.y = r.y + fmaf(pp, cr.y, e.y);
        v.z = r.z + fmaf(pp, cr.z, e.z);
        v.w = r.w + fmaf(pp, cr.w, e.w);
    }
    out[o] = v;
}

extern "C" void kernel_launch(void* const* d_in, const int* in_sizes, int n_in,
                              void* d_out, int out_size) {
    const float* hidden   = (const float*)d_in[0];  // (B,M,D)
    const float* residual = (const float*)d_in[1];  // (B,L,D)
    const float* prob     = (const float*)d_in[2];  // (B,L)
    const float* state    = (const float*)d_in[3];  // (B,D)
    const void*  mask     = d_in[4];                // (B,L) bool (width auto-detected)
    const int*   counts   = (const int*)d_in[5];    // (B,)

    float* out = (float*)d_out;
    const long long main_elems = (long long)Bn * Ln * Dn;
    float* ns = (out_size >= main_elems + Bn * Dn) ? (out + main_elems) : nullptr;

    k_prep  <<<Bn, 512>>>(prob, mask, counts);
    k_scan  <<<Bn * NC, 128>>>((const float4*)hidden);
    k_carry <<<Bn * Dn / 128, 128>>>(state, counts, ns);
    k_out   <<<Bn * Ln / 2, 256>>>((const float4*)residual, (float4*)out);
}

// round 10
// speedup vs baseline: 3.2678x; 1.2245x over previous
#include <cuda_runtime.h>

// Problem shape (fixed by the dataset)
#define Bn 8
#define Ln 4096
#define Mn 2048
#define Dn 512
#define CK 32              // chunk length along M
#define NC (Mn / CK)       // 64 chunks
#define D4 (Dn / 4)        // 128 float4 per row

// -------- device scratch (static globals: allocation-free) --------
__device__ float g_decay[Bn * Mn];        // per-chunk-slot decay (1.0 for invalid slots)
__device__ float g_pp[Bn * Mn];           // within-chunk inclusive prefix products of decay
__device__ float g_Ac[Bn * NC];           // per-chunk total decay product
__device__ float g_Bc[Bn * NC * Dn];      // per-chunk local scan result (h0 = 0)
__device__ float g_carry[Bn * NC * Dn];   // state entering each chunk
__device__ int   g_cidx[Bn * Ln];         // inclusive cumsum(token_mask) - 1  (>= -1)
__device__ float g_ema[Bn * Mn * Dn];     // local (h0=0) EMA states, all t

// -------- K1: per-batch compaction with in-block mask-width detection --------
__global__ __launch_bounds__(512) void k_prep(const float* __restrict__ prob,
                                              const void* __restrict__ maskbuf,
                                              const int* __restrict__ counts) {
    const int b   = blockIdx.x;
    const int tid = threadIdx.x;           // 512 threads, 8 tokens each
    const unsigned char* mb8  = (const unsigned char*)maskbuf;
    const int*           mb32 = (const int*)maskbuf;

    // ---- detect mask element width for this row:
    // u8 layout: nonzero bytes in bytes [b*Ln, (b+1)*Ln) == counts[b] (1024..2048).
    // i32 layout: those bytes cover 1024 ints (0/1 each) -> nonzero bytes <= 1024,
    // cannot equal counts[b]. ----
    __shared__ int wred[16];
    __shared__ int sflag;
    {
        int s = 0;
        for (int i = tid; i < Ln; i += 512) s += (mb8[b * Ln + i] != 0);
        #pragma unroll
        for (int o = 16; o; o >>= 1) s += __shfl_down_sync(0xFFFFFFFFu, s, o);
        if ((tid & 31) == 0) wred[tid >> 5] = s;
        __syncthreads();
        if (tid == 0) {
            int t = 0;
            #pragma unroll
            for (int w = 0; w < 16; w++) t += wred[w];
            sflag = (t == counts[b]) ? 1 : 0;
        }
        __syncthreads();
    }
    const int flag = sflag;

    int m[8];
    int s = 0;
    const int base = tid * 8;
    #pragma unroll
    for (int j = 0; j < 8; j++) {
        int l = base + j;
        int v = flag ? (mb8[b * Ln + l] != 0) : (mb32[b * Ln + l] != 0);
        m[j] = v;
        s += v;
    }

    // block-wide exclusive scan of per-thread counts
    const int lane = tid & 31, wid = tid >> 5;
    int inc = s;
    #pragma unroll
    for (int o = 1; o < 32; o <<= 1) {
        int n = __shfl_up_sync(0xFFFFFFFFu, inc, o);
        if (lane >= o) inc += n;
    }
    __shared__ int wsum[16];
    if (lane == 31) wsum[wid] = inc;
    __syncthreads();
    if (wid == 0 && lane < 16) {
        int v = wsum[lane];
        #pragma unroll
        for (int o = 1; o < 16; o <<= 1) {
            int n = __shfl_up_sync(0x0000FFFFu, v, o);
            if (lane >= o) v += n;
        }
        wsum[lane] = v;
    }
    __syncthreads();
    const int excl = inc - s + ((wid > 0) ? wsum[wid - 1] : 0);

    // init decay row to 1.0 (invalid slots: decay=1 -> state carries, matches ref)
    for (int i = tid; i < Mn; i += 512) g_decay[b * Mn + i] = 1.0f;
    __syncthreads();

    int run = excl;
    #pragma unroll
    for (int j = 0; j < 8; j++) {
        const int l = base + j;
        if (m[j]) {
            float p = prob[b * Ln + l];
            float dcy = fminf(fmaxf(1.0f - p, 0.0f), 1.0f);
            g_decay[b * Mn + run] = dcy;
            run++;
        }
        g_cidx[b * Ln + l] = run - 1;
    }
}

// -------- K2: per-chunk local EMA scan (h0 = 0), prefix products, A_c, B_c --------
__global__ __launch_bounds__(128) void k_scan(const float4* __restrict__ hidden) {
    const int blk = blockIdx.x;            // b*NC + c
    const int b = blk / NC, c = blk % NC;
    const int tid = threadIdx.x;           // 128 threads = one float4 column each

    __shared__ float sd[CK], sod[CK];
    if (tid < CK) {
        float d = g_decay[b * Mn + c * CK + tid];
        sd[tid]  = d;
        sod[tid] = 1.0f - d;
    }
    __syncthreads();

    if (tid == 0) {
        float p = 1.0f;
        #pragma unroll
        for (int t = 0; t < CK; t++) {
            p *= sd[t];
            g_pp[b * Mn + c * CK + t] = p;
        }
        g_Ac[blk] = p;
    }

    const size_t rowbase = (size_t)(b * Mn + c * CK) * D4 + tid;
    const float4* src = hidden + rowbase;
    float4*       dst = ((float4*)g_ema) + rowbase;

    // depth-8 prefetch ring; hidden is read-once -> streaming loads so the
    // ema/Bc writes keep L2 residency for k_out's gather.
    float4 buf[8];
    #pragma unroll
    for (int i = 0; i < 8; i++) buf[i] = __ldcs(&src[(size_t)i * D4]);

    float4 h = make_float4(0.f, 0.f, 0.f, 0.f);
    #pragma unroll
    for (int t = 0; t < CK; t++) {
        float4 x = buf[t & 7];
        if (t + 8 < CK) buf[t & 7] = __ldcs(&src[(size_t)(t + 8) * D4]);
        const float d = sd[t], od = sod[t];
        h.x = fmaf(d, h.x, od * x.x);
        h.y = fmaf(d, h.y, od * x.y);
        h.z = fmaf(d, h.z, od * x.z);
        h.w = fmaf(d, h.w, od * x.w);
        dst[(size_t)t * D4] = h;
    }
    ((float4*)g_Bc)[(size_t)blk * D4 + tid] = h;
}

// -------- K3: sequential chunk-carry combine + new_state --------
__global__ __launch_bounds__(128) void k_carry(const float* __restrict__ state,
                                               const int* __restrict__ counts,
                                               float* __restrict__ out_ns) {
    const int idx = blockIdx.x * 128 + threadIdx.x;   // (b,d) flat
    const int b = idx >> 9;          // / Dn
    const int d = idx & (Dn - 1);    // % Dn

    __shared__ float sA[NC];
    if (threadIdx.x < NC) sA[threadIdx.x] = g_Ac[b * NC + threadIdx.x];
    __syncthreads();

    const float* Bc = g_Bc    + (size_t)b * NC * Dn + d;
    float*       Cr = g_carry + (size_t)b * NC * Dn + d;

    float buf[NC];
    #pragma unroll
    for (int c = 0; c < NC; c++) buf[c] = __ldcg(&Bc[(size_t)c * Dn]);

    float carry = state[idx];
    #pragma unroll
    for (int c = 0; c < NC; c++) {
        Cr[(size_t)c * Dn] = carry;
        carry = fmaf(sA[c], carry, buf[c]);
    }

    if (out_ns) {
        const int cnt = counts[b];
        float ns;
        if (cnt > 0) {
            const int t = cnt - 1, cl = t / CK;
            ns = g_ema[(size_t)(b * Mn + t) * Dn + d] +
                 g_pp[b * Mn + t] * g_carry[(size_t)(b * NC + cl) * Dn + d];
        } else {
            ns = state[idx];
        }
        out_ns[idx] = ns;
    }
}

// -------- K4: gather + carry fix-up + residual add (2 rows per thread) --------
__global__ __launch_bounds__(256) void k_out(const float4* __restrict__ residual,
                                             float4* __restrict__ out) {
    const int t    = threadIdx.x & 127;
    const int pair = threadIdx.x >> 7;                  // 0 or 1
    const int row0 = blockIdx.x * 4 + pair * 2;         // rows row0, row0+1
    const int b    = row0 >> 12;                        // / Ln (same b for both rows)

    const int ci0 = g_cidx[row0];
    const int ci1 = g_cidx[row0 + 1];
    const int cc0 = max(ci0, 0), cc1 = max(ci1, 0);
    const float f0 = (ci0 >= 0) ? 1.0f : 0.0f;
    const float f1 = (ci1 >= 0) ? 1.0f : 0.0f;

    const size_t o0 = (size_t)row0 * D4 + t;
    const size_t o1 = o0 + D4;

    // issue all 6 float4 loads + 2 scalar loads back-to-back (MLP ~8)
    const float4 r0 = __ldcs(&residual[o0]);
    const float4 r1 = __ldcs(&residual[o1]);
    const float4 e0 = ((const float4*)g_ema)[(size_t)(b * Mn + cc0) * D4 + t];
    const float4 e1 = ((const float4*)g_ema)[(size_t)(b * Mn + cc1) * D4 + t];
    const float4 cr0 = ((const float4*)g_carry)[(size_t)(b * NC + (cc0 >> 5)) * D4 + t];
    const float4 cr1 = ((const float4*)g_carry)[(size_t)(b * NC + (cc1 >> 5)) * D4 + t];
    const float pp0 = g_pp[b * Mn + cc0];
    const float pp1 = g_pp[b * Mn + cc1];

    float4 v0, v1;
    v0.x = fmaf(f0, fmaf(pp0, cr0.x, e0.x), r0.x);
    v0.y = fmaf(f0, fmaf(pp0, cr0.y, e0.y), r0.y);
    v0.z = fmaf(f0, fmaf(pp0, cr0.z, e0.z), r0.z);
    v0.w = fmaf(f0, fmaf(pp0, cr0.w, e0.w), r0.w);
    v1.x = fmaf(f1, fmaf(pp1, cr1.x, e1.x), r1.x);
    v1.y = fmaf(f1, fmaf(pp1, cr1.y, e1.y), r1.y);
    v1.z = fmaf(f1, fmaf(pp1, cr1.z, e1.z), r1.z);
    v1.w = fmaf(f1, fmaf(pp1, cr1.w, e1.w), r1.w);

    __stcs(&out[o0], v0);
    __stcs(&out[o1], v1);
}

extern "C" void kernel_launch(void* const* d_in, const int* in_sizes, int n_in,
                              void* d_out, int out_size) {
    const float* hidden   = (const float*)d_in[0];  // (B,M,D)
    const float* residual = (const float*)d_in[1];  // (B,L,D)
    const float* prob     = (const float*)d_in[2];  // (B,L)
    const float* state    = (const float*)d_in[3];  // (B,D)
    const void*  mask     = d_in[4];                // (B,L) bool (width auto-detected)
    const int*   counts   = (const int*)d_in[5];    // (B,)

    float* out = (float*)d_out;
    const long long main_elems = (long long)Bn * Ln * Dn;
    float* ns = (out_size >= main_elems + Bn * Dn) ? (out + main_elems) : nullptr;

    k_prep  <<<Bn, 512>>>(prob, mask, counts);
    k_scan  <<<Bn * NC, 128>>>((const float4*)hidden);
    k_carry <<<Bn * Dn / 128, 128>>>(state, counts, ns);
    k_out   <<<Bn * Ln / 4, 256>>>((const float4*)residual, (float4*)out);
}